// round 12
// baseline (speedup 1.0000x reference)
#include <cuda_runtime.h>
#include <cuda_fp16.h>
#include <cstdint>

// ---------------------------------------------------------------------------
// Problem constants
// ---------------------------------------------------------------------------
#define BSZ      4
#define SEQ      4096
#define EMB      1024
#define HID      2048
#define FOURH    8192
#define MROWS    (BSZ*SEQ)      // 16384
#define NCH      (BSZ*HID)      // 8192 scan channels

// GEMM tile config (HMMA mma.sync — tcgen05 unavailable at .target sm_103)
#define BM 128
#define BN 128
#define BKK 64
#define ROWB 144                        // 128B data + 16B pad
#define A_MAT (128*ROWB)                // 18432
#define STAGE (2*A_MAT)                 // 36864
#define NSTAGE 3
#define SMEMG (NSTAGE*STAGE)            // 110592/CTA, 2 CTAs/SM
#define GTHREADS 128

// ---------------------------------------------------------------------------
// Scratch (static device globals)
// ---------------------------------------------------------------------------
__device__ __half g_yh[(size_t)MROWS * FOURH];  // GEMM1 out, fp16 (256MB)
__device__ float g_a [(size_t)NCH   * SEQ];
__device__ float g_b [(size_t)NCH   * SEQ];
__device__ float g_hs[(size_t)NCH   * SEQ];
__device__ __half g_xh [(size_t)MROWS * EMB];
__device__ __half g_w1h[(size_t)FOURH * EMB];
__device__ __half g_w2h[(size_t)EMB * HID];
__device__ __half g_gh [(size_t)MROWS * HID];

// ---------------------------------------------------------------------------
// PTX helpers (sm_80-baseline)
// ---------------------------------------------------------------------------
__device__ __forceinline__ uint32_t smem_u32(const void* p) {
    uint32_t a;
    asm("{ .reg .u64 t; cvta.to.shared.u64 t, %1; cvt.u32.u64 %0, t; }" : "=r"(a) : "l"(p));
    return a;
}
__device__ __forceinline__ void cp16(uint32_t s, const void* g) {
    asm volatile("cp.async.cg.shared.global [%0], [%1], 16;" :: "r"(s), "l"(g));
}
#define CP_COMMIT() asm volatile("cp.async.commit_group;" ::: "memory")
#define CP_WAIT(n)  asm volatile("cp.async.wait_group %0;" :: "n"(n) : "memory")

__device__ __forceinline__ void ldsm4(uint32_t& r0, uint32_t& r1, uint32_t& r2, uint32_t& r3,
                                      uint32_t addr) {
    asm volatile("ldmatrix.sync.aligned.m8n8.x4.shared.b16 {%0,%1,%2,%3}, [%4];"
                 : "=r"(r0), "=r"(r1), "=r"(r2), "=r"(r3) : "r"(addr));
}
__device__ __forceinline__ void mma16816(float* c, uint32_t a0, uint32_t a1, uint32_t a2,
                                         uint32_t a3, uint32_t b0, uint32_t b1) {
    asm volatile(
        "mma.sync.aligned.m16n8k16.row.col.f32.f16.f16.f32 "
        "{%0,%1,%2,%3}, {%4,%5,%6,%7}, {%8,%9}, {%0,%1,%2,%3};"
        : "+f"(c[0]), "+f"(c[1]), "+f"(c[2]), "+f"(c[3])
        : "r"(a0), "r"(a1), "r"(a2), "r"(a3), "r"(b0), "r"(b1));
}

// ---------------------------------------------------------------------------
// fp32 -> fp16 round
// ---------------------------------------------------------------------------
__global__ __launch_bounds__(256)
void round1_kernel(const float* __restrict__ in, __half* __restrict__ out, int n4)
{
    int i = blockIdx.x * 256 + threadIdx.x;
    if (i >= n4) return;
    float4 v = ((const float4*)in)[i];
    __half2* op = (__half2*)out;
    op[2*i]   = __half2(__float2half_rn(v.x), __float2half_rn(v.y));
    op[2*i+1] = __half2(__float2half_rn(v.z), __float2half_rn(v.w));
}

// ---------------------------------------------------------------------------
// HMMA fp16 GEMM: C[M,N] = A[M,K] @ B[N,K]^T.
// CTA tile 128x128, BK=64, 3-stage cp.async pipeline (1 sync/iter),
// 128 threads (4 warps), warp grid 2x2, warp tile 64x64, 2 CTAs/SM.
// OUTHALF=1: store C as fp16 (__half2); OUTHALF=0: fp32.
// ---------------------------------------------------------------------------
template <int OUTHALF>
__global__ __launch_bounds__(GTHREADS, 2)
void gemm_hmma_kernel(const __half* __restrict__ Ah,
                      const __half* __restrict__ Bh,
                      float* __restrict__ Cf, __half* __restrict__ Ch,
                      int N, int K)
{
    extern __shared__ char smem[];
    const uint32_t sbase = smem_u32(smem);
    const int tid  = threadIdx.x;
    const int wid  = tid >> 5;
    const int lane = tid & 31;
    const int bm = blockIdx.y * BM;
    const int bn = blockIdx.x * BN;
    const int wm = (wid >> 1) * 64;
    const int wn = (wid & 1) * 64;

    const int NC = K / BKK;

    const int lrow = tid >> 3;          // 0..15
    const int lch  = tid & 7;           // 0..7
    auto load_stage = [&](int kc, int buf) {
        const uint32_t sb = sbase + buf * STAGE;
        const int k0 = kc * BKK;
#pragma unroll
        for (int j = 0; j < 8; j++) {
            int r = lrow + j * 16;
            size_t goA = (size_t)(bm + r) * K + k0 + lch * 8;
            size_t goB = (size_t)(bn + r) * K + k0 + lch * 8;
            uint32_t so = sb + r * ROWB + lch * 16;
            cp16(so,         Ah + goA);
            cp16(so + A_MAT, Bh + goB);
        }
    };

    // ldmatrix lane addressing
    const int lr  = lane & 7;
    const int sel = lane >> 3;
    const uint32_t a_lane_off = (uint32_t)((wm + lr + ((sel & 1) << 3)) * ROWB + ((sel >> 1) << 4));
    const uint32_t b_lane_off = (uint32_t)(A_MAT + (wn + lr + ((sel >> 1) << 3)) * ROWB + ((sel & 1) << 4));

    float acc[4][8][4];
#pragma unroll
    for (int mt = 0; mt < 4; mt++)
#pragma unroll
        for (int nt = 0; nt < 8; nt++)
#pragma unroll
            for (int r = 0; r < 4; r++) acc[mt][nt][r] = 0.f;

    load_stage(0, 0); CP_COMMIT();
    load_stage(1, 1); CP_COMMIT();

    int buf = 0;
    for (int it = 0; it < NC; it++) {
        if (it + 1 < NC) { CP_WAIT(1); } else { CP_WAIT(0); }
        __syncthreads();

        if (it + 2 < NC) { load_stage(it + 2, (buf + 2) % NSTAGE); CP_COMMIT(); }

        const uint32_t sb = sbase + buf * STAGE;
#pragma unroll
        for (int ks = 0; ks < 4; ks++) {
            const uint32_t kofs = ks * 32;
            uint32_t ah[4][4];
#pragma unroll
            for (int mt = 0; mt < 4; mt++) {
                uint32_t addr = sb + a_lane_off + mt * (16 * ROWB) + kofs;
                ldsm4(ah[mt][0], ah[mt][1], ah[mt][2], ah[mt][3], addr);
            }
            // B double-buffer across ng
            uint32_t bcur[4], bnxt[4];
            ldsm4(bcur[0], bcur[1], bcur[2], bcur[3], sb + b_lane_off + kofs);
#pragma unroll
            for (int ng = 0; ng < 4; ng++) {
                if (ng < 3) {
                    uint32_t addr = sb + b_lane_off + (ng + 1) * (16 * ROWB) + kofs;
                    ldsm4(bnxt[0], bnxt[1], bnxt[2], bnxt[3], addr);
                }
#pragma unroll
                for (int mt = 0; mt < 4; mt++) {
#pragma unroll
                    for (int half = 0; half < 2; half++) {
                        float* a4 = acc[mt][ng * 2 + half];
                        mma16816(a4, ah[mt][0], ah[mt][1], ah[mt][2], ah[mt][3],
                                 bcur[half*2], bcur[half*2+1]);
                    }
                }
#pragma unroll
                for (int q = 0; q < 4; q++) bcur[q] = bnxt[q];
            }
        }
        buf = (buf + 1) % NSTAGE;
    }

    // Epilogue
    const int rrow = lane >> 2;
    const int rcol = (lane & 3) * 2;
#pragma unroll
    for (int mt = 0; mt < 4; mt++) {
        const int row0 = bm + wm + mt * 16 + rrow;
#pragma unroll
        for (int nt = 0; nt < 8; nt++) {
            const int col = bn + wn + nt * 8 + rcol;
            if (OUTHALF) {
                *(__half2*)(Ch + (size_t)row0 * N + col) =
                    __half2(__float2half_rn(acc[mt][nt][0]), __float2half_rn(acc[mt][nt][1]));
                *(__half2*)(Ch + (size_t)(row0 + 8) * N + col) =
                    __half2(__float2half_rn(acc[mt][nt][2]), __float2half_rn(acc[mt][nt][3]));
            } else {
                *(float2*)(Cf + (size_t)row0 * N + col)       = make_float2(acc[mt][nt][0], acc[mt][nt][1]);
                *(float2*)(Cf + (size_t)(row0 + 8) * N + col) = make_float2(acc[mt][nt][2], acc[mt][nt][3]);
            }
        }
    }
}

// ---------------------------------------------------------------------------
// Conv + gates (per-head f/i split), channel-major outputs  [C, S]
// ---------------------------------------------------------------------------
__global__ __launch_bounds__(256)
void conv_gate_kernel(const float* __restrict__ cw)
{
    __shared__ float s_a[32][33];
    __shared__ float s_b[32][33];

    const int c  = blockIdx.x * 32 + threadIdx.x;
    const int fc = ((c >> 7) << 8) | (c & 127);
    const int ic = fc + 128;
    const int b  = blockIdx.z;
    const int t0 = blockIdx.y * 32;

    float wf[4], wi[4];
#pragma unroll
    for (int k = 0; k < 4; k++) { wf[k] = cw[fc * 4 + k]; wi[k] = cw[ic * 4 + k]; }

#pragma unroll
    for (int it = 0; it < 4; ++it) {
        const int tl = threadIdx.y + it * 8;
        const int t  = t0 + tl;
        const size_t rowbase = ((size_t)(b * SEQ + t)) * FOURH;
        float accf = 0.f, acci = 0.f;
#pragma unroll
        for (int k = 0; k < 4; k++) {
            int tp = t - 3 + k;
            if (tp >= 0) {
                size_t rb2 = ((size_t)(b * SEQ + tp)) * FOURH;
                accf = fmaf(wf[k], __half2float(g_yh[rb2 + 4096 + fc]), accf);
                acci = fmaf(wi[k], __half2float(g_yh[rb2 + 4096 + ic]), acci);
            }
        }
        const float h = __half2float(g_yh[rowbase + 2048 + c]);
        const float f = 1.f / (1.f + __expf(-accf));
        const float i = 1.f / (1.f + __expf(-acci));
        const float denom = 1.f / (f + i + 1e-4f);
        s_a[tl][threadIdx.x] = f * denom;
        s_b[tl][threadIdx.x] = h * i * denom;
    }
    __syncthreads();

    const int lin = threadIdx.y * 32 + threadIdx.x;
    const int tw  = lin & 31;
    const int cb  = lin >> 5;
#pragma unroll
    for (int j = 0; j < 4; j++) {
        const int cl = cb + j * 8;
        const size_t idx = ((size_t)(b * HID + blockIdx.x * 32 + cl)) * SEQ + t0 + tw;
        g_a[idx] = s_a[tw][cl];
        g_b[idx] = s_b[tw][cl];
    }
}

// ---------------------------------------------------------------------------
// Linear scan per channel
// ---------------------------------------------------------------------------
__global__ __launch_bounds__(128)
void scan_kernel()
{
    const int ch  = blockIdx.x;
    const int tid = threadIdx.x;
    const size_t base = (size_t)ch * SEQ + (size_t)tid * 32;

    float a[32], bb[32];
#pragma unroll
    for (int j = 0; j < 32; j += 4) {
        float4 va = *(const float4*)(g_a + base + j);
        float4 vb = *(const float4*)(g_b + base + j);
        a[j+0]=va.x; a[j+1]=va.y; a[j+2]=va.z; a[j+3]=va.w;
        bb[j+0]=vb.x; bb[j+1]=vb.y; bb[j+2]=vb.z; bb[j+3]=vb.w;
    }

    float A = 1.f, Bv = 0.f;
#pragma unroll
    for (int j = 0; j < 32; j++) { Bv = fmaf(a[j], Bv, bb[j]); A *= a[j]; }

    __shared__ float sA[128], sB[128];
    sA[tid] = A; sB[tid] = Bv;
    __syncthreads();
    for (int off = 1; off < 128; off <<= 1) {
        float pA = 0.f, pB = 0.f;
        if (tid >= off) { pA = sA[tid - off]; pB = sB[tid - off]; }
        __syncthreads();
        if (tid >= off) { Bv = fmaf(A, pB, Bv); A = A * pA; sA[tid] = A; sB[tid] = Bv; }
        __syncthreads();
    }

    float h = (tid == 0) ? 0.f : sB[tid - 1];
#pragma unroll
    for (int j = 0; j < 32; j++) { h = fmaf(a[j], h, bb[j]); bb[j] = h; }
#pragma unroll
    for (int j = 0; j < 32; j += 4)
        *(float4*)(g_hs + base + j) = make_float4(bb[j], bb[j+1], bb[j+2], bb[j+3]);
}

// ---------------------------------------------------------------------------
// g = silu(out1) * out2 ; writes fp16 for GEMM2
// ---------------------------------------------------------------------------
__global__ __launch_bounds__(256)
void silu_mul_kernel()
{
    __shared__ float sm[32][33];
    const int c0 = blockIdx.x * 32;
    const int s0 = blockIdx.y * 32;
    const int b  = blockIdx.z;

#pragma unroll
    for (int it = 0; it < 4; ++it) {
        const int cl = threadIdx.y + it * 8;
        const int s  = s0 + threadIdx.x;
        sm[cl][threadIdx.x] = g_hs[((size_t)(b * HID + c0 + cl)) * SEQ + s];
    }
    __syncthreads();

#pragma unroll
    for (int it = 0; it < 4; ++it) {
        const int sl = threadIdx.y + it * 8;
        const int s  = s0 + sl;
        const int c  = c0 + threadIdx.x;
        const size_t row = (size_t)(b * SEQ + s);
        const float o1 = __half2float(g_yh[row * FOURH + c]);
        const float sil = o1 / (1.f + __expf(-o1));
        const float v = sil * sm[threadIdx.x][sl];
        g_gh[row * HID + c] = __float2half_rn(v);
    }
}

// ---------------------------------------------------------------------------
// Launch
// ---------------------------------------------------------------------------
extern "C" void kernel_launch(void* const* d_in, const int* in_sizes, int n_in,
                              void* d_out, int out_size)
{
    const float* x  = (const float*)d_in[0];
    const float* w1 = (const float*)d_in[1];
    const float* w2 = (const float*)d_in[2];
    const float* cw = (const float*)d_in[3];
    float* out = (float*)d_out;

    __half *yh, *xh, *w1h, *w2h, *gh;
    cudaGetSymbolAddress((void**)&yh,  g_yh);
    cudaGetSymbolAddress((void**)&xh,  g_xh);
    cudaGetSymbolAddress((void**)&w1h, g_w1h);
    cudaGetSymbolAddress((void**)&w2h, g_w2h);
    cudaGetSymbolAddress((void**)&gh,  g_gh);

    cudaFuncSetAttribute(gemm_hmma_kernel<0>, cudaFuncAttributeMaxDynamicSharedMemorySize, SMEMG);
    cudaFuncSetAttribute(gemm_hmma_kernel<1>, cudaFuncAttributeMaxDynamicSharedMemorySize, SMEMG);

    // conversions
    {
        int n4 = MROWS * EMB / 4;
        round1_kernel<<<(n4 + 255) / 256, 256>>>(x, xh, n4);
        n4 = FOURH * EMB / 4;
        round1_kernel<<<(n4 + 255) / 256, 256>>>(w1, w1h, n4);
        n4 = EMB * HID / 4;
        round1_kernel<<<(n4 + 255) / 256, 256>>>(w2, w2h, n4);
    }

    // GEMM1: y[M,8192] = x @ w1^T  (fp16 out)
    gemm_hmma_kernel<1><<<dim3(FOURH / BN, MROWS / BM), GTHREADS, SMEMG>>>(
        xh, w1h, nullptr, yh, FOURH, EMB);

    conv_gate_kernel<<<dim3(HID / 32, SEQ / 32, BSZ), dim3(32, 8)>>>(cw);
    scan_kernel<<<NCH, 128>>>();
    silu_mul_kernel<<<dim3(HID / 32, SEQ / 32, BSZ), dim3(32, 8)>>>();

    // GEMM2: out[M,1024] = g @ w2^T  (fp32 out)
    gemm_hmma_kernel<0><<<dim3(EMB / BN, MROWS / BM), GTHREADS, SMEMG>>>(
        gh, w2h, out, nullptr, EMB, HID);
}